// round 15
// baseline (speedup 1.0000x reference)
#include <cuda_runtime.h>
#include <cstdint>

#define H    512
#define G4   2048
#define SEQL 1024
#define EMB  300
#define NCTA 64
#define TPB  256

// Scratch: 8 MB gate-precompute (transposed [t][u][gate]) + 4 MB tagged-h ring.
__device__ float g_xg4[SEQL * G4];
__device__ __align__(16) unsigned long long g_htag[SEQL * H];

// ---------------------------------------------------------------------------
// Kernel 1: xg[t][u][g] = (b_ih[r]+b_hh[r]) + sum_e emb[tok[t]][e]*W_ih[r][e],
// r = g*512+u. 64x64 tile per block, 4x4 micro-tile per thread.
// ---------------------------------------------------------------------------
#define TK 16
__global__ __launch_bounds__(256) void xgemm_kernel(
    const int* __restrict__ tokens,
    const float* __restrict__ emb,
    const float* __restrict__ Wih,
    const float* __restrict__ bih,
    const float* __restrict__ bhh)
{
    __shared__ float Ws[64][TK + 1];
    __shared__ float Xs[64][TK + 1];
    __shared__ int   toks[64];

    const int row0 = blockIdx.x * 64;
    const int t0   = blockIdx.y * 64;
    const int tid  = threadIdx.x;
    const int tx = tid & 15, ty = tid >> 4;

    if (tid < 64) toks[tid] = tokens[t0 + tid];
    __syncthreads();

    float acc[4][4];
#pragma unroll
    for (int i = 0; i < 4; i++)
#pragma unroll
        for (int j = 0; j < 4; j++) acc[i][j] = 0.f;

    const int kk = tid & 15;
    const int ib = tid >> 4;

    for (int k0 = 0; k0 < EMB; k0 += TK) {
#pragma unroll
        for (int q = 0; q < 4; q++) {
            int i = ib + q * 16;
            int e = k0 + kk;
            long widx = (long)(row0 + i) * EMB + (e < EMB ? e : EMB - 1);
            Ws[i][kk] = Wih[widx];
            Xs[i][kk] = (e < EMB) ? emb[(long)toks[i] * EMB + e] : 0.f;
        }
        __syncthreads();
#pragma unroll
        for (int k = 0; k < TK; k++) {
            float a[4], x[4];
#pragma unroll
            for (int i = 0; i < 4; i++) a[i] = Ws[tx * 4 + i][k];
#pragma unroll
            for (int j = 0; j < 4; j++) x[j] = Xs[ty * 4 + j][k];
#pragma unroll
            for (int i = 0; i < 4; i++)
#pragma unroll
                for (int j = 0; j < 4; j++)
                    acc[i][j] += a[i] * x[j];
        }
        __syncthreads();
    }

#pragma unroll
    for (int i = 0; i < 4; i++) {
        int row = row0 + tx * 4 + i;
        float bias = bih[row] + bhh[row];
        int u = row & 511, g = row >> 9;
#pragma unroll
        for (int j = 0; j < 4; j++) {
            int t = t0 + ty * 4 + j;
            g_xg4[(long)t * G4 + u * 4 + g] = acc[i][j] + bias;   // [t][u][gate]
        }
    }
}

// ---------------------------------------------------------------------------
// packed fp32x2 FMA (sm_103a; only via PTX)
// ---------------------------------------------------------------------------
__device__ __forceinline__ void ffma2(unsigned long long& d,
                                      unsigned long long a, unsigned long long b)
{
    asm("fma.rn.f32x2 %0, %1, %2, %3;" : "=l"(d) : "l"(a), "l"(b), "l"(d));
}

__device__ __forceinline__ float fast_tanh(float x)
{
    float a = fabsf(x);
    float e = __expf(-2.f * a);
    float r = __fdividef(1.f - e, 1.f + e);
    return copysignf(r, x);
}
__device__ __forceinline__ float fast_sigmoid(float x)
{
    return __fdividef(1.f, 1.f + __expf(-x));
}

#define POLL_LD(r0, r1, p) \
    asm volatile("ld.volatile.global.v2.u64 {%0,%1},[%2];" \
                 : "=l"(r0), "=l"(r1) : "l"(p))
#define POLL_PAUSE(n) do { unsigned _s = (unsigned)clock(); \
    while ((unsigned)clock() - _s < (n)) { } } while (0)

// ---------------------------------------------------------------------------
// Kernel 2: persistent LSTM recurrence — R4 champion skeleton (3-barrier
// lockstep, warp-0 coalesced publish) with a 3-STREAM PIPELINED POLL.
//
// Why: bar1 releases at the MAX over 256 threads of poll-detect time.
// A serialized poll has period = one L2 round trip (~400 cyc), so the max
// detection slack ~= a full period on top of the round trip. Keeping 3
// staggered loads of the same 16B in flight drops the check grid to
// ~130 cyc: each round checks the oldest stream (stalling only until it
// arrives), reissues it, pauses ~130, checks the next. Fast path (tag
// already present) hits the first check with zero added latency.
// ---------------------------------------------------------------------------
// smem h layout: h[k] stored at f(k) = 18*(k>>4) + (k&15)  (max 573 -> 576)
__global__ __launch_bounds__(TPB, 1) void lstm_kernel(
    const int* __restrict__ tokens,
    const float* __restrict__ h0,
    const float* __restrict__ c0,
    const float* __restrict__ Whh,
    float* __restrict__ out)
{
    __shared__ __align__(16) float h_s[576];
    __shared__ float gates_s[32];
    __shared__ int   toks[SEQL];

    const int b    = blockIdx.x;
    const int tid  = threadIdx.x;
    const int w    = tid >> 5;
    const int lane = tid & 31;

    for (int i = tid; i < SEQL; i += TPB) toks[i] = tokens[i];

    // Weights: warp w -> gate g=w>>1, rows rbase..rbase+3; lane covers
    // K in [16*lane, 16*lane+16) as 8 f32x2 pairs.
    const int rbase = (w >> 1) * H + b * 8 + 4 * (w & 1);
    unsigned long long wp[4][8];
#pragma unroll
    for (int i = 0; i < 4; i++) {
        const float* wrow = Whh + (size_t)(rbase + i) * H + 16 * lane;
#pragma unroll
        for (int j = 0; j < 8; j++) {
            float2 f = *(const float2*)(wrow + 2 * j);
            unsigned long long v;
            asm("mov.b64 %0, {%1,%2};" : "=l"(v) : "f"(f.x), "f"(f.y));
            wp[i][j] = v;
        }
    }

    float c_reg = 0.f, h_last = 0.f, out_reg = 0.f;
    if (tid < 8) {
        c_reg  = c0[b * 8 + tid];
        h_last = h0[b * 8 + tid];
    }

    unsigned long long* htag = g_htag;

    for (int t = 0; t < SEQL; t++) {
        // Publisher threads prefetch their 4 gate biases (1 LDG.128),
        // latency hidden behind the poll below.
        float4 xgv = make_float4(0.f, 0.f, 0.f, 0.f);
        if (tid < 8)
            xgv = *(const float4*)(g_xg4 + (size_t)t * G4 + (b * 8 + tid) * 4);

        // Acquire h_{t-1} into padded smem (thread handles k0=2tid, k0+1).
        {
            const int k0 = 2 * tid;
            float* dst = &h_s[18 * (k0 >> 4) + (k0 & 15)];
            if (t == 0) {
                *(float2*)dst = *(const float2*)(h0 + k0);
            } else {
                const unsigned long long* ptr =
                    htag + (size_t)(t - 1) * H + k0;
                const unsigned tag = (unsigned)t;
                unsigned long long pa0, pa1, pb0, pb1, pc0, pc1, v0, v1;
                // 3-stream pipelined poll (see header).
                POLL_LD(pa0, pa1, ptr);
                POLL_LD(pb0, pb1, ptr);
                POLL_LD(pc0, pc1, ptr);
                for (;;) {
                    if ((unsigned)(pa0 >> 32) == tag &&
                        (unsigned)(pa1 >> 32) == tag) { v0 = pa0; v1 = pa1; break; }
                    POLL_LD(pa0, pa1, ptr);
                    POLL_PAUSE(130u);
                    if ((unsigned)(pb0 >> 32) == tag &&
                        (unsigned)(pb1 >> 32) == tag) { v0 = pb0; v1 = pb1; break; }
                    POLL_LD(pb0, pb1, ptr);
                    POLL_PAUSE(130u);
                    if ((unsigned)(pc0 >> 32) == tag &&
                        (unsigned)(pc1 >> 32) == tag) { v0 = pc0; v1 = pc1; break; }
                    POLL_LD(pc0, pc1, ptr);
                }
                float2 hv;
                hv.x = __uint_as_float((unsigned)v0);
                hv.y = __uint_as_float((unsigned)v1);
                *(float2*)dst = hv;
            }
        }
        __syncthreads();                              // bar1

        // Dot: 4 gate rows x 16 K per thread, f32x2 FMAs, weights in regs.
        unsigned long long a0 = 0ull, a1 = 0ull, a2 = 0ull, a3 = 0ull;
        const unsigned long long* hb =
            (const unsigned long long*)&h_s[18 * lane];
#pragma unroll
        for (int j = 0; j < 8; j++) {
            unsigned long long hv = hb[j];            // h[16*lane+2j], h[+1]
            ffma2(a0, wp[0][j], hv);
            ffma2(a1, wp[1][j], hv);
            ffma2(a2, wp[2][j], hv);
            ffma2(a3, wp[3][j], hv);
        }
        float acc0, acc1, acc2, acc3;
        {
            float lo, hi;
            asm("mov.b64 {%0,%1}, %2;" : "=f"(lo), "=f"(hi) : "l"(a0)); acc0 = lo + hi;
            asm("mov.b64 {%0,%1}, %2;" : "=f"(lo), "=f"(hi) : "l"(a1)); acc1 = lo + hi;
            asm("mov.b64 {%0,%1}, %2;" : "=f"(lo), "=f"(hi) : "l"(a2)); acc2 = lo + hi;
            asm("mov.b64 {%0,%1}, %2;" : "=f"(lo), "=f"(hi) : "l"(a3)); acc3 = lo + hi;
        }
#pragma unroll
        for (int off = 16; off > 0; off >>= 1) {
            acc0 += __shfl_xor_sync(0xffffffffu, acc0, off);
            acc1 += __shfl_xor_sync(0xffffffffu, acc1, off);
            acc2 += __shfl_xor_sync(0xffffffffu, acc2, off);
            acc3 += __shfl_xor_sync(0xffffffffu, acc3, off);
        }
        if (lane == 0) {
            gates_s[w * 4 + 0] = acc0;
            gates_s[w * 4 + 1] = acc1;
            gates_s[w * 4 + 2] = acc2;
            gates_s[w * 4 + 3] = acc3;
        }
        __syncthreads();                              // bar2

        if (tid < 8) {
            const int k = tid;
            float si = fast_sigmoid(gates_s[k]      + xgv.x);
            float sf = fast_sigmoid(gates_s[8 + k]  + xgv.y);
            float tg = fast_tanh   (gates_s[16 + k] + xgv.z);
            float so = fast_sigmoid(gates_s[24 + k] + xgv.w);
            float c_new = sf * c_reg + si * tg;
            float h_new = so * fast_tanh(c_new);
            if (toks[t] != 1) {                 // PAD_IDX == 1
                c_reg  = c_new;
                h_last = h_new;
                out_reg = h_new;
            }
            unsigned long long v =
                ((unsigned long long)(unsigned)(t + 1) << 32) |
                (unsigned long long)__float_as_uint(h_last);
            htag[(size_t)t * H + b * 8 + k] = v;
        }
        __syncthreads();   // bar3: park everyone, publisher warp owns SMSP
    }

    if (tid < 8) {
        out[b * 8 + tid]         = out_reg;  // out
        out[H + b * 8 + tid]     = h_last;   // h
        out[2 * H + b * 8 + tid] = c_reg;    // c
    }
}

extern "C" void kernel_launch(void* const* d_in, const int* in_sizes, int n_in,
                              void* d_out, int out_size)
{
    const int*   tokens = (const int*)  d_in[0];
    const float* h0     = (const float*)d_in[1];
    const float* c0     = (const float*)d_in[2];
    const float* emb    = (const float*)d_in[3];
    const float* Wih    = (const float*)d_in[4];
    const float* Whh    = (const float*)d_in[5];
    const float* bih    = (const float*)d_in[6];
    const float* bhh    = (const float*)d_in[7];
    float* out = (float*)d_out;

    // Reset the tag buffer every launch (deterministic across graph replays).
    void* htag_ptr = nullptr;
    cudaGetSymbolAddress(&htag_ptr, g_htag);
    cudaMemsetAsync(htag_ptr, 0, sizeof(unsigned long long) * SEQL * H);

    dim3 g1(G4 / 64, SEQL / 64);
    xgemm_kernel<<<g1, 256>>>(tokens, emb, Wih, bih, bhh);
    lstm_kernel<<<NCTA, TPB>>>(tokens, h0, c0, Whh, out);
}